// round 14
// baseline (speedup 1.0000x reference)
#include <cuda_runtime.h>
#include <cuda_fp16.h>
#include <math.h>
#include <stdint.h>

#define LMAXV 10
#define NSH 121
#define MAXN 131072
#define HID 512

// ---------------- scratch (device globals; no allocations allowed) ----------------
__device__ __align__(16) __half g_hA[(size_t)MAXN * HID];
__device__ __align__(16) __half g_hB[(size_t)MAXN * HID];
__device__ __align__(16) __half g_wh[3][512 * 512];
__device__ __align__(16) __half g_wc16[512 * 32];

// ---------------- compile-time SH constants ----------------
struct SHTab {
    float F[LMAXV + 1][LMAXV + 1];
    float DF[LMAXV + 1];
};
constexpr double cfact(int n) { double r = 1.0; for (int i = 2; i <= n; ++i) r *= (double)i; return r; }
constexpr double cdfact(int n) { double r = 1.0; while (n > 0) { r *= (double)n; n -= 2; } return r; }
constexpr double csqrt_(double x) { double g = (x > 1.0) ? x : 1.0; for (int i = 0; i < 200; ++i) g = 0.5 * (g + x / g); return g; }
constexpr double PI_D = 3.14159265358979323846;
constexpr SHTab mk_shtab() {
    SHTab t{};
    for (int m = 0; m <= LMAXV; ++m) t.DF[m] = (float)cdfact(2 * m - 1);
    for (int l = 0; l <= LMAXV; ++l)
        for (int m = 0; m <= l; ++m) {
            double K = csqrt_((2.0 * l + 1.0) / (4.0 * PI_D) * cfact(l - m) / cfact(l + m));
            t.F[l][m] = (float)((m == 0) ? K : csqrt_(2.0) * K);
        }
    return t;
}
__constant__ SHTab SHT = mk_shtab();
__constant__ float LAMB[LMAXV + 1] = {
    3.1415926535897927f, 2.0943951023931957f, 0.7853981633974483f, 0.0f,
    -0.13089969389957473f, 0.0f, 0.04908738521234052f, 0.0f,
    -0.024543692606170262f, 0.0f, 0.014317154020265985f
};

__device__ __forceinline__ float sigm(float x) { return 1.0f / (1.0f + expf(-x)); }
__device__ __forceinline__ float softplus_f(float x) { return fmaxf(x, 0.0f) + log1pf(expf(-fabsf(x))); }

// ---------------- kernel 1: SH dots only (independent of MLP chain) ----------------
__global__ __launch_bounds__(256) void sh_kernel(
    const float* __restrict__ normals, const float* __restrict__ view_dirs,
    const float* __restrict__ feature, const float* __restrict__ refsh,
    float* __restrict__ out, int N)
{
    int n = blockIdx.x * blockDim.x + threadIdx.x;
    if (n >= N) return;

    float nx = normals[3 * n + 0], ny = normals[3 * n + 1], nz = normals[3 * n + 2];
    float vx = view_dirs[3 * n + 0], vy = view_dirs[3 * n + 1], vz = view_dirs[3 * n + 2];
    float dt = nx * vx + ny * vy + nz * vz;
    float wx = 2.0f * nx * dt - vx;
    float wy = 2.0f * ny * dt - vy;
    float wz = 2.0f * nz * dt - vz;

    const float* f = feature + (size_t)n * 16;
    float rough = softplus_f(f[0]);
    float a0 = sigm(f[10]), a1 = sigm(f[11]), a2 = sigm(f[12]);

    float inv1 = rsqrtf(nx * nx + ny * ny + nz * nz);
    float x1 = nx * inv1, y1 = ny * inv1, z1 = nz * inv1;
    float inv2 = rsqrtf(wx * wx + wy * wy + wz * wz);
    float x2 = wx * inv2, y2 = wy * inv2, z2 = wz * inv2;

    float ca[LMAXV + 1], sa_[LMAXV + 1], cb[LMAXV + 1], sb_[LMAXV + 1];
    ca[0] = 1.f; sa_[0] = 0.f; cb[0] = 1.f; sb_[0] = 0.f;
#pragma unroll
    for (int m = 1; m <= LMAXV; ++m) {
        ca[m] = x1 * ca[m - 1] - y1 * sa_[m - 1];
        sa_[m] = x1 * sa_[m - 1] + y1 * ca[m - 1];
        cb[m] = x2 * cb[m - 1] - y2 * sb_[m - 1];
        sb_[m] = x2 * sb_[m - 1] + y2 * cb[m - 1];
    }

    float Qm1a[LMAXV + 1], Qm2a[LMAXV + 1], Qm1b[LMAXV + 1], Qm2b[LMAXV + 1];

    float e = expf(-rough);
    float pe = 1.0f;
    float dcur = 1.0f;

    const float* r = refsh + (size_t)n * (NSH * 3);

    float ix = 0.f, iy = 0.f, iz = 0.f;
    float lx = 0.f, ly = 0.f, lz = 0.f;

#pragma unroll
    for (int l = 0; l <= LMAXV; ++l) {
        float Qa[LMAXV + 1], Qb[LMAXV + 1];
#pragma unroll
        for (int m = 0; m <= l; ++m) {
            if (m == l) {
                Qa[m] = SHT.DF[l]; Qb[m] = SHT.DF[l];
            } else if (m == l - 1) {
                Qa[m] = (float)(2 * m + 1) * z1 * Qm1a[m];
                Qb[m] = (float)(2 * m + 1) * z2 * Qm1b[m];
            } else {
                float il = 1.0f / (float)(l - m);
                Qa[m] = ((float)(2 * l - 1) * z1 * Qm1a[m] - (float)(l + m - 1) * Qm2a[m]) * il;
                Qb[m] = ((float)(2 * l - 1) * z2 * Qm1b[m] - (float)(l + m - 1) * Qm2b[m]) * il;
            }
        }

        float wla = LAMB[l];
        float wlb = dcur;
        const float* rl = r + 3 * (l * l);
#pragma unroll
        for (int j = 0; j <= 2 * l; ++j) {
            int m = (j < l) ? (l - j) : (j - l);
            float fk = SHT.F[l][m];
            float qa = fk * Qa[m], qb = fk * Qb[m];
            float ta, tb;
            if (j < l)      { ta = wla * qa * sa_[m]; tb = wlb * qb * sb_[m]; }
            else if (j == l){ ta = wla * qa;          tb = wlb * qb; }
            else            { ta = wla * qa * ca[m];  tb = wlb * qb * cb[m]; }
            float r0 = rl[3 * j + 0], r1 = rl[3 * j + 1], r2 = rl[3 * j + 2];
            ix = fmaf(ta, r0, ix); iy = fmaf(ta, r1, iy); iz = fmaf(ta, r2, iz);
            lx = fmaf(tb, r0, lx); ly = fmaf(tb, r1, ly); lz = fmaf(tb, r2, lz);
        }

#pragma unroll
        for (int m = 0; m <= l; ++m) {
            Qm2a[m] = Qm1a[m]; Qm1a[m] = Qa[m];
            Qm2b[m] = Qm1b[m]; Qm1b[m] = Qb[m];
        }
        pe *= e;
        dcur *= pe;
    }

    ix = fmaxf(ix, 0.f); iy = fmaxf(iy, 0.f); iz = fmaxf(iz, 0.f);
    lx = fmaxf(lx, 0.f); ly = fmaxf(ly, 0.f); lz = fmaxf(lz, 0.f);

    size_t N3 = 3 * (size_t)N;
    out[1 * N3 + 3 * n + 0] = a0;      out[1 * N3 + 3 * n + 1] = a1;      out[1 * N3 + 3 * n + 2] = a2;
    out[2 * N3 + 3 * n + 0] = a0 * ix; out[2 * N3 + 3 * n + 1] = a1 * iy; out[2 * N3 + 3 * n + 2] = a2 * iz;
    out[4 * N3 + 3 * n + 0] = lx;      out[4 * N3 + 3 * n + 1] = ly;      out[4 * N3 + 3 * n + 2] = lz;
    out[5 * N3 + 3 * n + 0] = ix;      out[5 * N3 + 3 * n + 1] = iy;      out[5 * N3 + 3 * n + 2] = iz;
}

// ---------------- kernel 2: layer0 (computes h8 inline, 8 -> 512) ----------------
__global__ __launch_bounds__(256) void layer0_kernel(
    const float* __restrict__ normals, const float* __restrict__ view_dirs,
    const float* __restrict__ feature, const float* __restrict__ w0,
    const float* __restrict__ b0, __half* __restrict__ outp, int N)
{
    __shared__ float hs[128][8];
    int tid = threadIdx.x;
    int n0 = blockIdx.x * 128;

    if (tid < 128) {
        int n = n0 + tid;
        float nx = normals[3 * n + 0], ny = normals[3 * n + 1], nz = normals[3 * n + 2];
        float vx = view_dirs[3 * n + 0], vy = view_dirs[3 * n + 1], vz = view_dirs[3 * n + 2];
        float dt = nx * vx + ny * vy + nz * vz;
        float rough = softplus_f(feature[(size_t)n * 16]);
        hs[tid][0] = dt; hs[tid][1] = vx; hs[tid][2] = vy; hs[tid][3] = vz;
        hs[tid][4] = nx; hs[tid][5] = ny; hs[tid][6] = nz; hs[tid][7] = rough;
    }

    int c0 = tid * 2;
    float wreg[8][2];
#pragma unroll
    for (int i = 0; i < 8; ++i) {
        wreg[i][0] = w0[i * 512 + c0];
        wreg[i][1] = w0[i * 512 + c0 + 1];
    }
    float bias0 = b0[c0], bias1 = b0[c0 + 1];

    __syncthreads();

#pragma unroll 4
    for (int p = 0; p < 128; ++p) {
        float acc0 = bias0, acc1 = bias1;
#pragma unroll
        for (int i = 0; i < 8; ++i) {
            float h = hs[p][i];
            acc0 = fmaf(h, wreg[i][0], acc0);
            acc1 = fmaf(h, wreg[i][1], acc1);
        }
        __half2 hv = __floats2half2_rn(fmaxf(acc0, 0.0f), fmaxf(acc1, 0.0f));
        *(__half2*)(outp + (size_t)(n0 + p) * 512 + c0) = hv;
    }
}

// ---------------- merged weight fp32 -> fp16 (w1,w2,w3 + padded wc) ----------------
__global__ __launch_bounds__(256) void cvt_all_kernel(
    const float* __restrict__ w1, const float* __restrict__ w2,
    const float* __restrict__ w3, const float* __restrict__ wc,
    __half* __restrict__ owh, __half* __restrict__ owc)
{
    int i = blockIdx.x * 256 + threadIdx.x;
    if (i < 786432) {
        const float* src = (i < 262144) ? w1 : (i < 524288) ? w2 : w3;
        owh[i] = __float2half_rn(src[i & 262143]);
    } else {
        int j = i - 786432;               // 0..16383
        int r = j >> 5, c = j & 31;
        owc[j] = (c < 27) ? __float2half_rn(wc[r * 27 + c]) : __float2half_rn(0.0f);
    }
}

// ---------------- common mma helpers ----------------
__device__ __forceinline__ uint32_t smem_u32(const void* p) {
    uint32_t a;
    asm("{ .reg .u64 t; cvta.to.shared.u64 t, %1; cvt.u32.u64 %0, t; }" : "=r"(a) : "l"(p));
    return a;
}
__device__ __forceinline__ void cp16(uint32_t dst, const void* src) {
    asm volatile("cp.async.cg.shared.global [%0], [%1], 16;\n" :: "r"(dst), "l"(src));
}
#define LDSM4(r0, r1, r2, r3, addr) \
    asm volatile("ldmatrix.sync.aligned.m8n8.x4.shared.b16 {%0,%1,%2,%3}, [%4];" \
                 : "=r"(r0), "=r"(r1), "=r"(r2), "=r"(r3) : "r"(addr))
#define LDSM4T(r0, r1, r2, r3, addr) \
    asm volatile("ldmatrix.sync.aligned.m8n8.x4.trans.shared.b16 {%0,%1,%2,%3}, [%4];" \
                 : "=r"(r0), "=r"(r1), "=r"(r2), "=r"(r3) : "r"(addr))
#define MMA16816(d, a, b0v, b1v) \
    asm volatile("mma.sync.aligned.m16n8k16.row.col.f32.f16.f16.f32 " \
                 "{%0,%1,%2,%3}, {%4,%5,%6,%7}, {%8,%9}, {%0,%1,%2,%3};" \
                 : "+f"((d)[0]), "+f"((d)[1]), "+f"((d)[2]), "+f"((d)[3]) \
                 : "r"((a)[0]), "r"((a)[1]), "r"((a)[2]), "r"((a)[3]), "r"(b0v), "r"(b1v))

// ---------------- fp16 mma.sync GEMM, K=64 per pipeline stage (R8/R12 config) -----
#define SA_STAGE 18432     // 128 * 144
#define SB_STAGE 16384     // 64 * 256
#define SB_BASE  55296     // 3 * SA_STAGE
#define SM_MMA   104448    // SB_BASE + 3 * SB_STAGE

__device__ __forceinline__ void mma_load_stage(int kt, int tid, uint32_t sb,
                                               const __half* Ab, const __half* Wb)
{
    int s = kt % 3;
    uint32_t sa = sb + s * SA_STAGE;
    uint32_t sbm = sb + SB_BASE + s * SB_STAGE;
    int k0 = kt * 64;
#pragma unroll
    for (int t = 0; t < 4; ++t) {
        int i = tid + t * 256;
        int r = i >> 3, c = i & 7;
        cp16(sa + (uint32_t)(r * 144 + c * 16), Ab + (size_t)r * 512 + k0 + c * 8);
    }
#pragma unroll
    for (int t = 0; t < 4; ++t) {
        int i = tid + t * 256;
        int r = i >> 4, c8 = i & 15;
        cp16(sbm + (uint32_t)((r * 16 + (c8 ^ (r & 7))) * 16),
             Wb + (size_t)(k0 + r) * 512 + c8 * 8);
    }
    asm volatile("cp.async.commit_group;\n" ::: "memory");
}

__global__ __launch_bounds__(256, 2)
void mma512_kernel(const __half* __restrict__ A, const __half* __restrict__ W,
                   const float* __restrict__ bias, __half* __restrict__ C)
{
    extern __shared__ __align__(128) char smem[];
    uint32_t sb = smem_u32(smem);
    int tid = threadIdx.x, l = tid & 31, w = tid >> 5;
    int bx = blockIdx.x, by = blockIdx.y;
    int wm = (w >> 1) * 32, wn = (w & 1) * 64;

    const __half* Ab = A + (size_t)by * 128 * 512;
    const __half* Wb = W + bx * 128;

    float acc[2][8][4];
#pragma unroll
    for (int i = 0; i < 2; ++i)
#pragma unroll
        for (int j = 0; j < 8; ++j)
#pragma unroll
            for (int q = 0; q < 4; ++q) acc[i][j][q] = 0.0f;

    uint32_t la = (uint32_t)((wm + (l & 7) + ((l >> 3) & 1) * 8) * 144 + ((l >> 4) & 1) * 16);
    int rb = (l & 7) + ((l >> 3) & 1) * 8;
    uint32_t lb[4];
#pragma unroll
    for (int p = 0; p < 4; ++p) {
        int c8b = (wn >> 3) + p * 2 + ((l >> 4) & 1);
        lb[p] = (uint32_t)(rb * 256 + ((c8b ^ (rb & 7)) * 16));
    }

    mma_load_stage(0, tid, sb, Ab, Wb);
    mma_load_stage(1, tid, sb, Ab, Wb);

#pragma unroll
    for (int kt = 0; kt < 8; ++kt) {
        if (kt < 7) asm volatile("cp.async.wait_group 1;\n" ::: "memory");
        else        asm volatile("cp.async.wait_group 0;\n" ::: "memory");
        __syncthreads();
        if (kt < 6) mma_load_stage(kt + 2, tid, sb, Ab, Wb);

        int s = kt % 3;
        uint32_t sa = sb + s * SA_STAGE + la;
        uint32_t sbm = sb + SB_BASE + s * SB_STAGE;
#pragma unroll
        for (int kk = 0; kk < 4; ++kk) {
            uint32_t a0[4], a1[4];
            LDSM4(a0[0], a0[1], a0[2], a0[3], sa + kk * 32);
            LDSM4(a1[0], a1[1], a1[2], a1[3], sa + 2304 + kk * 32);
#pragma unroll
            for (int p = 0; p < 4; ++p) {
                uint32_t b0, b1, b2, b3;
                LDSM4T(b0, b1, b2, b3, sbm + kk * 4096 + lb[p]);
                MMA16816(acc[0][p * 2 + 0], a0, b0, b1);
                MMA16816(acc[0][p * 2 + 1], a0, b2, b3);
                MMA16816(acc[1][p * 2 + 0], a1, b0, b1);
                MMA16816(acc[1][p * 2 + 1], a1, b2, b3);
            }
        }
    }

    // epilogue: bias + relu -> fp16
#pragma unroll
    for (int mt = 0; mt < 2; ++mt) {
        int row = by * 128 + wm + mt * 16 + (l >> 2);
#pragma unroll
        for (int nt = 0; nt < 8; ++nt) {
            int col = bx * 128 + wn + nt * 8 + (l & 3) * 2;
            float bs0 = __ldg(bias + col), bs1 = __ldg(bias + col + 1);
            float* d = acc[mt][nt];
            __half2 h01 = __floats2half2_rn(fmaxf(d[0] + bs0, 0.0f), fmaxf(d[1] + bs1, 0.0f));
            __half2 h23 = __floats2half2_rn(fmaxf(d[2] + bs0, 0.0f), fmaxf(d[3] + bs1, 0.0f));
            *(__half2*)(C + (size_t)row * 512 + col) = h01;
            *(__half2*)(C + (size_t)(row + 8) * 512 + col) = h23;
        }
    }
}

// ---------------- kernel 4: final layer (512->27) HMMA, FUSED with finalize -------
#define W27_B   0          // B: 512 * 80 = 40960
#define W27_A   40960      // A: 3 stages * 10240 = 30720
#define W27_CS  71680      // cs tile: 128 * 28 * 4 = 14336
#define SM_27   86016

__global__ __launch_bounds__(256, 2)
void mma27_kernel(const __half* __restrict__ A, const __half* __restrict__ wc16,
                  const float* __restrict__ bc, const float* __restrict__ feature,
                  float* __restrict__ out, int N)
{
    extern __shared__ __align__(128) char smem[];
    uint32_t sb = smem_u32(smem);
    float* cs_s = (float*)(smem + W27_CS);
    int tid = threadIdx.x, l = tid & 31, w = tid >> 5;
    int by = blockIdx.x;

    const __half* Ab = A + (size_t)by * 128 * 512;

#pragma unroll
    for (int t = 0; t < 8; ++t) {
        int i = tid + t * 256;
        int r = i >> 2, c = i & 3;
        cp16(sb + W27_B + (uint32_t)(r * 80 + c * 16), wc16 + (size_t)r * 32 + c * 8);
    }
    asm volatile("cp.async.commit_group;\n" ::: "memory");

    auto loadA = [&](int kt) {
        int s = kt % 3;
        uint32_t sa = sb + W27_A + s * 10240;
#pragma unroll
        for (int t = 0; t < 2; ++t) {
            int i = tid + t * 256;
            int r = i >> 2, c = i & 3;
            cp16(sa + (uint32_t)(r * 80 + c * 16), Ab + (size_t)r * 512 + kt * 32 + c * 8);
        }
        asm volatile("cp.async.commit_group;\n" ::: "memory");
    };
    loadA(0);
    loadA(1);

    float acc[4][4];
#pragma unroll
    for (int i = 0; i < 4; ++i)
#pragma unroll
        for (int q = 0; q < 4; ++q) acc[i][q] = 0.0f;

    uint32_t la = (uint32_t)((w * 16 + (l & 7) + ((l >> 3) & 1) * 8) * 80 + ((l >> 4) & 1) * 16);
    int rb = (l & 7) + ((l >> 3) & 1) * 8;
    uint32_t cchunk = (uint32_t)(((l >> 4) & 1) * 16);

#pragma unroll
    for (int kt = 0; kt < 16; ++kt) {
        if (kt < 15) asm volatile("cp.async.wait_group 1;\n" ::: "memory");
        else         asm volatile("cp.async.wait_group 0;\n" ::: "memory");
        __syncthreads();
        if (kt < 14) loadA(kt + 2);

        int s = kt % 3;
        uint32_t sa = sb + W27_A + s * 10240 + la;
#pragma unroll
        for (int kk = 0; kk < 2; ++kk) {
            uint32_t a[4];
            LDSM4(a[0], a[1], a[2], a[3], sa + kk * 32);
            uint32_t baddr = sb + W27_B + (uint32_t)((kt * 32 + kk * 16 + rb) * 80) + cchunk;
            uint32_t b0, b1, b2, b3, c0, c1, c2, c3;
            LDSM4T(b0, b1, b2, b3, baddr);
            LDSM4T(c0, c1, c2, c3, baddr + 32);
            MMA16816(acc[0], a, b0, b1);
            MMA16816(acc[1], a, b2, b3);
            MMA16816(acc[2], a, c0, c1);
            MMA16816(acc[3], a, c2, c3);
        }
    }

    // stage cs tile (with bias) into smem
    __syncthreads();
#pragma unroll
    for (int nt = 0; nt < 4; ++nt) {
        int col = nt * 8 + (l & 3) * 2;
        int lr = w * 16 + (l >> 2);
#pragma unroll
        for (int h = 0; h < 2; ++h) {
            int rr = lr + h * 8;
            if (col < 27)     cs_s[rr * 28 + col]     = acc[nt][h * 2 + 0] + __ldg(bc + col);
            if (col + 1 < 27) cs_s[rr * 28 + col + 1] = acc[nt][h * 2 + 1] + __ldg(bc + col + 1);
        }
    }
    __syncthreads();

    // fused finalize: threads 0..127, one row each
    if (tid < 128) {
        int n = by * 128 + tid;
        const float* f = feature + (size_t)n * 16;
        float coe[9];
#pragma unroll
        for (int i = 0; i < 9; ++i) coe[i] = f[1 + i];
        float sp0 = sigm(f[13]), sp1 = sigm(f[14]), sp2 = sigm(f[15]);

        const float* c = cs_s + tid * 28;
        float rr = 0.f, gg = 0.f, bb = 0.f;
#pragma unroll
        for (int i = 0; i < 9; ++i) {
            rr = fmaf(c[i], coe[i], rr);
            gg = fmaf(c[9 + i], coe[i], gg);
            bb = fmaf(c[18 + i], coe[i], bb);
        }
        float g0 = sigm(rr), g1 = sigm(gg), g2 = sigm(bb);

        size_t N3 = 3 * (size_t)N;
        float l0 = out[4 * N3 + 3 * n + 0];
        float l1 = out[4 * N3 + 3 * n + 1];
        float l2 = out[4 * N3 + 3 * n + 2];
        float d0 = out[2 * N3 + 3 * n + 0];
        float d1 = out[2 * N3 + 3 * n + 1];
        float d2 = out[2 * N3 + 3 * n + 2];

        float s0 = sp0 * l0 * g0;
        float s1 = sp1 * l1 * g1;
        float s2 = sp2 * l2 * g2;

        out[3 * N3 + 3 * n + 0] = s0;
        out[3 * N3 + 3 * n + 1] = s1;
        out[3 * N3 + 3 * n + 2] = s2;
        out[0 * N3 + 3 * n + 0] = d0 + s0;
        out[0 * N3 + 3 * n + 1] = d1 + s1;
        out[0 * N3 + 3 * n + 2] = d2 + s2;
    }
}

// ---------------- launch ----------------
extern "C" void kernel_launch(void* const* d_in, const int* in_sizes, int n_in,
                              void* d_out, int out_size)
{
    const float* normals   = (const float*)d_in[0];
    const float* view_dirs = (const float*)d_in[1];
    const float* feature   = (const float*)d_in[2];
    const float* ref_SH    = (const float*)d_in[3];
    const float* w0 = (const float*)d_in[4];
    const float* b0 = (const float*)d_in[5];
    const float* w1 = (const float*)d_in[6];
    const float* b1 = (const float*)d_in[7];
    const float* w2 = (const float*)d_in[8];
    const float* b2 = (const float*)d_in[9];
    const float* w3 = (const float*)d_in[10];
    const float* b3 = (const float*)d_in[11];
    const float* wc = (const float*)d_in[12];
    const float* bc = (const float*)d_in[13];

    int N = in_sizes[0] / 3;
    float* out = (float*)d_out;

    __half *hA, *hB, *whp, *wcp;
    cudaGetSymbolAddress((void**)&hA, g_hA);
    cudaGetSymbolAddress((void**)&hB, g_hB);
    cudaGetSymbolAddress((void**)&whp, g_wh);
    cudaGetSymbolAddress((void**)&wcp, g_wc16);

    cudaFuncSetAttribute(mma512_kernel, cudaFuncAttributeMaxDynamicSharedMemorySize, SM_MMA);
    cudaFuncSetAttribute(mma27_kernel, cudaFuncAttributeMaxDynamicSharedMemorySize, SM_27);

    static cudaStream_t s2 = nullptr;
    static cudaEvent_t evFork = nullptr, evCvt = nullptr, evJoin = nullptr;
    if (s2 == nullptr) {
        cudaStreamCreateWithFlags(&s2, cudaStreamNonBlocking);
        cudaEventCreateWithFlags(&evFork, cudaEventDisableTiming);
        cudaEventCreateWithFlags(&evCvt, cudaEventDisableTiming);
        cudaEventCreateWithFlags(&evJoin, cudaEventDisableTiming);
    }

    __half* w1h = whp + 0 * 262144;
    __half* w2h = whp + 1 * 262144;
    __half* w3h = whp + 2 * 262144;

    // fork: weight conversion + SH dot kernel run on s2, concurrent with layer0
    cudaEventRecord(evFork, 0);
    cudaStreamWaitEvent(s2, evFork, 0);
    cvt_all_kernel<<<(786432 + 16384) / 256, 256, 0, s2>>>(w1, w2, w3, wc, whp, wcp);
    cudaEventRecord(evCvt, s2);
    sh_kernel<<<(N + 255) / 256, 256, 0, s2>>>(normals, view_dirs, feature, ref_SH, out, N);
    cudaEventRecord(evJoin, s2);

    // main chain (tensor-bound)
    layer0_kernel<<<N / 128, 256>>>(normals, view_dirs, feature, w0, b0, hA, N);

    // weights must be converted before first GEMM (covered by layer0's duration)
    cudaStreamWaitEvent(0, evCvt, 0);
    dim3 gm(4, N / 128);
    mma512_kernel<<<gm, 256, SM_MMA>>>(hA, w1h, b1, hB);
    mma512_kernel<<<gm, 256, SM_MMA>>>(hB, w2h, b2, hA);
    mma512_kernel<<<gm, 256, SM_MMA>>>(hA, w3h, b3, hB);

    // join before fused mma27+finalize (it reads sh outputs)
    cudaStreamWaitEvent(0, evJoin, 0);
    mma27_kernel<<<N / 128, 256, SM_27>>>(hB, wcp, bc, feature, out, N);
}

// round 15
// speedup vs baseline: 1.5146x; 1.5146x over previous
#include <cuda_runtime.h>
#include <cuda_fp16.h>
#include <math.h>
#include <stdint.h>

#define LMAXV 10
#define NSH 121
#define MAXN 131072
#define HID 512

// ---------------- scratch (device globals; no allocations allowed) ----------------
__device__ __align__(16) __half g_hA[(size_t)MAXN * HID];
__device__ __align__(16) __half g_hB[(size_t)MAXN * HID];
__device__ __align__(16) __half g_wh[3][512 * 512];
__device__ __align__(16) __half g_wc16[512 * 32];

// ---------------- compile-time SH constants ----------------
struct SHTab {
    float F[LMAXV + 1][LMAXV + 1];
    float DF[LMAXV + 1];
};
constexpr double cfact(int n) { double r = 1.0; for (int i = 2; i <= n; ++i) r *= (double)i; return r; }
constexpr double cdfact(int n) { double r = 1.0; while (n > 0) { r *= (double)n; n -= 2; } return r; }
constexpr double csqrt_(double x) { double g = (x > 1.0) ? x : 1.0; for (int i = 0; i < 200; ++i) g = 0.5 * (g + x / g); return g; }
constexpr double PI_D = 3.14159265358979323846;
constexpr SHTab mk_shtab() {
    SHTab t{};
    for (int m = 0; m <= LMAXV; ++m) t.DF[m] = (float)cdfact(2 * m - 1);
    for (int l = 0; l <= LMAXV; ++l)
        for (int m = 0; m <= l; ++m) {
            double K = csqrt_((2.0 * l + 1.0) / (4.0 * PI_D) * cfact(l - m) / cfact(l + m));
            t.F[l][m] = (float)((m == 0) ? K : csqrt_(2.0) * K);
        }
    return t;
}
__constant__ SHTab SHT = mk_shtab();
__constant__ float LAMB[LMAXV + 1] = {
    3.1415926535897927f, 2.0943951023931957f, 0.7853981633974483f, 0.0f,
    -0.13089969389957473f, 0.0f, 0.04908738521234052f, 0.0f,
    -0.024543692606170262f, 0.0f, 0.014317154020265985f
};

__device__ __forceinline__ float sigm(float x) { return 1.0f / (1.0f + expf(-x)); }
__device__ __forceinline__ float softplus_f(float x) { return fmaxf(x, 0.0f) + log1pf(expf(-fabsf(x))); }

// ---------------- kernel 1: SH dots, grid-stride (low SM footprint) ----------------
__global__ __launch_bounds__(256) void sh_kernel(
    const float* __restrict__ normals, const float* __restrict__ view_dirs,
    const float* __restrict__ feature, const float* __restrict__ refsh,
    float* __restrict__ out, int N)
{
    for (int n = blockIdx.x * blockDim.x + threadIdx.x; n < N; n += gridDim.x * blockDim.x) {

    float nx = normals[3 * n + 0], ny = normals[3 * n + 1], nz = normals[3 * n + 2];
    float vx = view_dirs[3 * n + 0], vy = view_dirs[3 * n + 1], vz = view_dirs[3 * n + 2];
    float dt = nx * vx + ny * vy + nz * vz;
    float wx = 2.0f * nx * dt - vx;
    float wy = 2.0f * ny * dt - vy;
    float wz = 2.0f * nz * dt - vz;

    const float* f = feature + (size_t)n * 16;
    float rough = softplus_f(f[0]);
    float a0 = sigm(f[10]), a1 = sigm(f[11]), a2 = sigm(f[12]);

    float inv1 = rsqrtf(nx * nx + ny * ny + nz * nz);
    float x1 = nx * inv1, y1 = ny * inv1, z1 = nz * inv1;
    float inv2 = rsqrtf(wx * wx + wy * wy + wz * wz);
    float x2 = wx * inv2, y2 = wy * inv2, z2 = wz * inv2;

    float ca[LMAXV + 1], sa_[LMAXV + 1], cb[LMAXV + 1], sb_[LMAXV + 1];
    ca[0] = 1.f; sa_[0] = 0.f; cb[0] = 1.f; sb_[0] = 0.f;
#pragma unroll
    for (int m = 1; m <= LMAXV; ++m) {
        ca[m] = x1 * ca[m - 1] - y1 * sa_[m - 1];
        sa_[m] = x1 * sa_[m - 1] + y1 * ca[m - 1];
        cb[m] = x2 * cb[m - 1] - y2 * sb_[m - 1];
        sb_[m] = x2 * sb_[m - 1] + y2 * cb[m - 1];
    }

    float Qm1a[LMAXV + 1], Qm2a[LMAXV + 1], Qm1b[LMAXV + 1], Qm2b[LMAXV + 1];

    float e = expf(-rough);
    float pe = 1.0f;
    float dcur = 1.0f;

    const float* r = refsh + (size_t)n * (NSH * 3);

    float ix = 0.f, iy = 0.f, iz = 0.f;
    float lx = 0.f, ly = 0.f, lz = 0.f;

#pragma unroll
    for (int l = 0; l <= LMAXV; ++l) {
        float Qa[LMAXV + 1], Qb[LMAXV + 1];
#pragma unroll
        for (int m = 0; m <= l; ++m) {
            if (m == l) {
                Qa[m] = SHT.DF[l]; Qb[m] = SHT.DF[l];
            } else if (m == l - 1) {
                Qa[m] = (float)(2 * m + 1) * z1 * Qm1a[m];
                Qb[m] = (float)(2 * m + 1) * z2 * Qm1b[m];
            } else {
                float il = 1.0f / (float)(l - m);
                Qa[m] = ((float)(2 * l - 1) * z1 * Qm1a[m] - (float)(l + m - 1) * Qm2a[m]) * il;
                Qb[m] = ((float)(2 * l - 1) * z2 * Qm1b[m] - (float)(l + m - 1) * Qm2b[m]) * il;
            }
        }

        float wla = LAMB[l];
        float wlb = dcur;
        const float* rl = r + 3 * (l * l);
#pragma unroll
        for (int j = 0; j <= 2 * l; ++j) {
            int m = (j < l) ? (l - j) : (j - l);
            float fk = SHT.F[l][m];
            float qa = fk * Qa[m], qb = fk * Qb[m];
            float ta, tb;
            if (j < l)      { ta = wla * qa * sa_[m]; tb = wlb * qb * sb_[m]; }
            else if (j == l){ ta = wla * qa;          tb = wlb * qb; }
            else            { ta = wla * qa * ca[m];  tb = wlb * qb * cb[m]; }
            float r0 = rl[3 * j + 0], r1 = rl[3 * j + 1], r2 = rl[3 * j + 2];
            ix = fmaf(ta, r0, ix); iy = fmaf(ta, r1, iy); iz = fmaf(ta, r2, iz);
            lx = fmaf(tb, r0, lx); ly = fmaf(tb, r1, ly); lz = fmaf(tb, r2, lz);
        }

#pragma unroll
        for (int m = 0; m <= l; ++m) {
            Qm2a[m] = Qm1a[m]; Qm1a[m] = Qa[m];
            Qm2b[m] = Qm1b[m]; Qm1b[m] = Qb[m];
        }
        pe *= e;
        dcur *= pe;
    }

    ix = fmaxf(ix, 0.f); iy = fmaxf(iy, 0.f); iz = fmaxf(iz, 0.f);
    lx = fmaxf(lx, 0.f); ly = fmaxf(ly, 0.f); lz = fmaxf(lz, 0.f);

    size_t N3 = 3 * (size_t)N;
    out[1 * N3 + 3 * n + 0] = a0;      out[1 * N3 + 3 * n + 1] = a1;      out[1 * N3 + 3 * n + 2] = a2;
    out[2 * N3 + 3 * n + 0] = a0 * ix; out[2 * N3 + 3 * n + 1] = a1 * iy; out[2 * N3 + 3 * n + 2] = a2 * iz;
    out[4 * N3 + 3 * n + 0] = lx;      out[4 * N3 + 3 * n + 1] = ly;      out[4 * N3 + 3 * n + 2] = lz;
    out[5 * N3 + 3 * n + 0] = ix;      out[5 * N3 + 3 * n + 1] = iy;      out[5 * N3 + 3 * n + 2] = iz;

    }
}

// ---------------- kernel 2: layer0 (computes h8 inline, 8 -> 512) ----------------
__global__ __launch_bounds__(256) void layer0_kernel(
    const float* __restrict__ normals, const float* __restrict__ view_dirs,
    const float* __restrict__ feature, const float* __restrict__ w0,
    const float* __restrict__ b0, __half* __restrict__ outp, int N)
{
    __shared__ float hs[128][8];
    int tid = threadIdx.x;
    int n0 = blockIdx.x * 128;

    if (tid < 128) {
        int n = n0 + tid;
        float nx = normals[3 * n + 0], ny = normals[3 * n + 1], nz = normals[3 * n + 2];
        float vx = view_dirs[3 * n + 0], vy = view_dirs[3 * n + 1], vz = view_dirs[3 * n + 2];
        float dt = nx * vx + ny * vy + nz * vz;
        float rough = softplus_f(feature[(size_t)n * 16]);
        hs[tid][0] = dt; hs[tid][1] = vx; hs[tid][2] = vy; hs[tid][3] = vz;
        hs[tid][4] = nx; hs[tid][5] = ny; hs[tid][6] = nz; hs[tid][7] = rough;
    }

    int c0 = tid * 2;
    float wreg[8][2];
#pragma unroll
    for (int i = 0; i < 8; ++i) {
        wreg[i][0] = w0[i * 512 + c0];
        wreg[i][1] = w0[i * 512 + c0 + 1];
    }
    float bias0 = b0[c0], bias1 = b0[c0 + 1];

    __syncthreads();

#pragma unroll 4
    for (int p = 0; p < 128; ++p) {
        float acc0 = bias0, acc1 = bias1;
#pragma unroll
        for (int i = 0; i < 8; ++i) {
            float h = hs[p][i];
            acc0 = fmaf(h, wreg[i][0], acc0);
            acc1 = fmaf(h, wreg[i][1], acc1);
        }
        __half2 hv = __floats2half2_rn(fmaxf(acc0, 0.0f), fmaxf(acc1, 0.0f));
        *(__half2*)(outp + (size_t)(n0 + p) * 512 + c0) = hv;
    }
}

// ---------------- weight fp32 -> fp16 ----------------
__global__ __launch_bounds__(256) void cvtw_kernel(
    const float* __restrict__ w1, const float* __restrict__ w2,
    const float* __restrict__ w3, __half* __restrict__ o)
{
    int i = blockIdx.x * 256 + threadIdx.x;
    const float* src = (i < 262144) ? w1 : (i < 524288) ? w2 : w3;
    int j = i & 262143;
    o[i] = __float2half_rn(src[j]);
}

__global__ __launch_bounds__(256) void cvtwc_kernel(
    const float* __restrict__ wc, __half* __restrict__ o)
{
    int i = blockIdx.x * 256 + threadIdx.x;
    int r = i >> 5, c = i & 31;
    o[i] = (c < 27) ? __float2half_rn(wc[r * 27 + c]) : __float2half_rn(0.0f);
}

// ---------------- common mma helpers ----------------
__device__ __forceinline__ uint32_t smem_u32(const void* p) {
    uint32_t a;
    asm("{ .reg .u64 t; cvta.to.shared.u64 t, %1; cvt.u32.u64 %0, t; }" : "=r"(a) : "l"(p));
    return a;
}
__device__ __forceinline__ void cp16(uint32_t dst, const void* src) {
    asm volatile("cp.async.cg.shared.global [%0], [%1], 16;\n" :: "r"(dst), "l"(src));
}
#define LDSM4(r0, r1, r2, r3, addr) \
    asm volatile("ldmatrix.sync.aligned.m8n8.x4.shared.b16 {%0,%1,%2,%3}, [%4];" \
                 : "=r"(r0), "=r"(r1), "=r"(r2), "=r"(r3) : "r"(addr))
#define LDSM4T(r0, r1, r2, r3, addr) \
    asm volatile("ldmatrix.sync.aligned.m8n8.x4.trans.shared.b16 {%0,%1,%2,%3}, [%4];" \
                 : "=r"(r0), "=r"(r1), "=r"(r2), "=r"(r3) : "r"(addr))
#define MMA16816(d, a, b0v, b1v) \
    asm volatile("mma.sync.aligned.m16n8k16.row.col.f32.f16.f16.f32 " \
                 "{%0,%1,%2,%3}, {%4,%5,%6,%7}, {%8,%9}, {%0,%1,%2,%3};" \
                 : "+f"((d)[0]), "+f"((d)[1]), "+f"((d)[2]), "+f"((d)[3]) \
                 : "r"((a)[0]), "r"((a)[1]), "r"((a)[2]), "r"((a)[3]), "r"(b0v), "r"(b1v))

// ---------------- fp16 mma.sync GEMM, K=64 per pipeline stage (R12 config) --------
#define SA_STAGE 18432     // 128 * 144
#define SB_STAGE 16384     // 64 * 256
#define SB_BASE  55296     // 3 * SA_STAGE
#define SM_MMA   104448    // SB_BASE + 3 * SB_STAGE

__device__ __forceinline__ void mma_load_stage(int kt, int tid, uint32_t sb,
                                               const __half* Ab, const __half* Wb)
{
    int s = kt % 3;
    uint32_t sa = sb + s * SA_STAGE;
    uint32_t sbm = sb + SB_BASE + s * SB_STAGE;
    int k0 = kt * 64;
#pragma unroll
    for (int t = 0; t < 4; ++t) {
        int i = tid + t * 256;
        int r = i >> 3, c = i & 7;
        cp16(sa + (uint32_t)(r * 144 + c * 16), Ab + (size_t)r * 512 + k0 + c * 8);
    }
#pragma unroll
    for (int t = 0; t < 4; ++t) {
        int i = tid + t * 256;
        int r = i >> 4, c8 = i & 15;
        cp16(sbm + (uint32_t)((r * 16 + (c8 ^ (r & 7))) * 16),
             Wb + (size_t)(k0 + r) * 512 + c8 * 8);
    }
    asm volatile("cp.async.commit_group;\n" ::: "memory");
}

__global__ __launch_bounds__(256, 2)
void mma512_kernel(const __half* __restrict__ A, const __half* __restrict__ W,
                   const float* __restrict__ bias, __half* __restrict__ C)
{
    extern __shared__ __align__(128) char smem[];
    uint32_t sb = smem_u32(smem);
    int tid = threadIdx.x, l = tid & 31, w = tid >> 5;
    int bx = blockIdx.x, by = blockIdx.y;
    int wm = (w >> 1) * 32, wn = (w & 1) * 64;

    const __half* Ab = A + (size_t)by * 128 * 512;
    const __half* Wb = W + bx * 128;

    float acc[2][8][4];
#pragma unroll
    for (int i = 0; i < 2; ++i)
#pragma unroll
        for (int j = 0; j < 8; ++j)
#pragma unroll
            for (int q = 0; q < 4; ++q) acc[i][j][q] = 0.0f;

    uint32_t la = (uint32_t)((wm + (l & 7) + ((l >> 3) & 1) * 8) * 144 + ((l >> 4) & 1) * 16);
    int rb = (l & 7) + ((l >> 3) & 1) * 8;
    uint32_t lb[4];
#pragma unroll
    for (int p = 0; p < 4; ++p) {
        int c8b = (wn >> 3) + p * 2 + ((l >> 4) & 1);
        lb[p] = (uint32_t)(rb * 256 + ((c8b ^ (rb & 7)) * 16));
    }

    mma_load_stage(0, tid, sb, Ab, Wb);
    mma_load_stage(1, tid, sb, Ab, Wb);

#pragma unroll
    for (int kt = 0; kt < 8; ++kt) {
        if (kt < 7) asm volatile("cp.async.wait_group 1;\n" ::: "memory");
        else        asm volatile("cp.async.wait_group 0;\n" ::: "memory");
        __syncthreads();
        if (kt < 6) mma_load_stage(kt + 2, tid, sb, Ab, Wb);

        int s = kt % 3;
        uint32_t sa = sb + s * SA_STAGE + la;
        uint32_t sbm = sb + SB_BASE + s * SB_STAGE;
#pragma unroll
        for (int kk = 0; kk < 4; ++kk) {
            uint32_t a0[4], a1[4];
            LDSM4(a0[0], a0[1], a0[2], a0[3], sa + kk * 32);
            LDSM4(a1[0], a1[1], a1[2], a1[3], sa + 2304 + kk * 32);
#pragma unroll
            for (int p = 0; p < 4; ++p) {
                uint32_t b0, b1, b2, b3;
                LDSM4T(b0, b1, b2, b3, sbm + kk * 4096 + lb[p]);
                MMA16816(acc[0][p * 2 + 0], a0, b0, b1);
                MMA16816(acc[0][p * 2 + 1], a0, b2, b3);
                MMA16816(acc[1][p * 2 + 0], a1, b0, b1);
                MMA16816(acc[1][p * 2 + 1], a1, b2, b3);
            }
        }
    }

    // epilogue: bias + relu -> fp16
#pragma unroll
    for (int mt = 0; mt < 2; ++mt) {
        int row = by * 128 + wm + mt * 16 + (l >> 2);
#pragma unroll
        for (int nt = 0; nt < 8; ++nt) {
            int col = bx * 128 + wn + nt * 8 + (l & 3) * 2;
            float bs0 = __ldg(bias + col), bs1 = __ldg(bias + col + 1);
            float* d = acc[mt][nt];
            __half2 h01 = __floats2half2_rn(fmaxf(d[0] + bs0, 0.0f), fmaxf(d[1] + bs1, 0.0f));
            __half2 h23 = __floats2half2_rn(fmaxf(d[2] + bs0, 0.0f), fmaxf(d[3] + bs1, 0.0f));
            *(__half2*)(C + (size_t)row * 512 + col) = h01;
            *(__half2*)(C + (size_t)(row + 8) * 512 + col) = h23;
        }
    }
}

// ---------------- kernel 4: final layer (512->27) HMMA, FUSED with finalize -------
#define W27_B   0          // B: 512 * 80 = 40960
#define W27_A   40960      // A: 3 stages * 10240 = 30720
#define W27_CS  71680      // cs tile: 128 * 28 * 4 = 14336
#define SM_27   86016

__global__ __launch_bounds__(256, 2)
void mma27_kernel(const __half* __restrict__ A, const __half* __restrict__ wc16,
                  const float* __restrict__ bc, const float* __restrict__ feature,
                  float* __restrict__ out, int N)
{
    extern __shared__ __align__(128) char smem[];
    uint32_t sb = smem_u32(smem);
    float* cs_s = (float*)(smem + W27_CS);
    int tid = threadIdx.x, l = tid & 31, w = tid >> 5;
    int by = blockIdx.x;

    const __half* Ab = A + (size_t)by * 128 * 512;

#pragma unroll
    for (int t = 0; t < 8; ++t) {
        int i = tid + t * 256;
        int r = i >> 2, c = i & 3;
        cp16(sb + W27_B + (uint32_t)(r * 80 + c * 16), wc16 + (size_t)r * 32 + c * 8);
    }
    asm volatile("cp.async.commit_group;\n" ::: "memory");

    auto loadA = [&](int kt) {
        int s = kt % 3;
        uint32_t sa = sb + W27_A + s * 10240;
#pragma unroll
        for (int t = 0; t < 2; ++t) {
            int i = tid + t * 256;
            int r = i >> 2, c = i & 3;
            cp16(sa + (uint32_t)(r * 80 + c * 16), Ab + (size_t)r * 512 + kt * 32 + c * 8);
        }
        asm volatile("cp.async.commit_group;\n" ::: "memory");
    };
    loadA(0);
    loadA(1);

    float acc[4][4];
#pragma unroll
    for (int i = 0; i < 4; ++i)
#pragma unroll
        for (int q = 0; q < 4; ++q) acc[i][q] = 0.0f;

    uint32_t la = (uint32_t)((w * 16 + (l & 7) + ((l >> 3) & 1) * 8) * 80 + ((l >> 4) & 1) * 16);
    int rb = (l & 7) + ((l >> 3) & 1) * 8;
    uint32_t cchunk = (uint32_t)(((l >> 4) & 1) * 16);

#pragma unroll
    for (int kt = 0; kt < 16; ++kt) {
        if (kt < 15) asm volatile("cp.async.wait_group 1;\n" ::: "memory");
        else         asm volatile("cp.async.wait_group 0;\n" ::: "memory");
        __syncthreads();
        if (kt < 14) loadA(kt + 2);

        int s = kt % 3;
        uint32_t sa = sb + W27_A + s * 10240 + la;
#pragma unroll
        for (int kk = 0; kk < 2; ++kk) {
            uint32_t a[4];
            LDSM4(a[0], a[1], a[2], a[3], sa + kk * 32);
            uint32_t baddr = sb + W27_B + (uint32_t)((kt * 32 + kk * 16 + rb) * 80) + cchunk;
            uint32_t b0, b1, b2, b3, c0, c1, c2, c3;
            LDSM4T(b0, b1, b2, b3, baddr);
            LDSM4T(c0, c1, c2, c3, baddr + 32);
            MMA16816(acc[0], a, b0, b1);
            MMA16816(acc[1], a, b2, b3);
            MMA16816(acc[2], a, c0, c1);
            MMA16816(acc[3], a, c2, c3);
        }
    }

    // stage cs tile (with bias) into smem
    __syncthreads();
#pragma unroll
    for (int nt = 0; nt < 4; ++nt) {
        int col = nt * 8 + (l & 3) * 2;
        int lr = w * 16 + (l >> 2);
#pragma unroll
        for (int h = 0; h < 2; ++h) {
            int rr = lr + h * 8;
            if (col < 27)     cs_s[rr * 28 + col]     = acc[nt][h * 2 + 0] + __ldg(bc + col);
            if (col + 1 < 27) cs_s[rr * 28 + col + 1] = acc[nt][h * 2 + 1] + __ldg(bc + col + 1);
        }
    }
    __syncthreads();

    // fused finalize: threads 0..127, one row each
    if (tid < 128) {
        int n = by * 128 + tid;
        const float* f = feature + (size_t)n * 16;
        float coe[9];
#pragma unroll
        for (int i = 0; i < 9; ++i) coe[i] = f[1 + i];
        float sp0 = sigm(f[13]), sp1 = sigm(f[14]), sp2 = sigm(f[15]);

        const float* c = cs_s + tid * 28;
        float rr = 0.f, gg = 0.f, bb = 0.f;
#pragma unroll
        for (int i = 0; i < 9; ++i) {
            rr = fmaf(c[i], coe[i], rr);
            gg = fmaf(c[9 + i], coe[i], gg);
            bb = fmaf(c[18 + i], coe[i], bb);
        }
        float g0 = sigm(rr), g1 = sigm(gg), g2 = sigm(bb);

        size_t N3 = 3 * (size_t)N;
        float l0 = out[4 * N3 + 3 * n + 0];
        float l1 = out[4 * N3 + 3 * n + 1];
        float l2 = out[4 * N3 + 3 * n + 2];
        float d0 = out[2 * N3 + 3 * n + 0];
        float d1 = out[2 * N3 + 3 * n + 1];
        float d2 = out[2 * N3 + 3 * n + 2];

        float s0 = sp0 * l0 * g0;
        float s1 = sp1 * l1 * g1;
        float s2 = sp2 * l2 * g2;

        out[3 * N3 + 3 * n + 0] = s0;
        out[3 * N3 + 3 * n + 1] = s1;
        out[3 * N3 + 3 * n + 2] = s2;
        out[0 * N3 + 3 * n + 0] = d0 + s0;
        out[0 * N3 + 3 * n + 1] = d1 + s1;
        out[0 * N3 + 3 * n + 2] = d2 + s2;
    }
}

// ---------------- launch ----------------
extern "C" void kernel_launch(void* const* d_in, const int* in_sizes, int n_in,
                              void* d_out, int out_size)
{
    const float* normals   = (const float*)d_in[0];
    const float* view_dirs = (const float*)d_in[1];
    const float* feature   = (const float*)d_in[2];
    const float* ref_SH    = (const float*)d_in[3];
    const float* w0 = (const float*)d_in[4];
    const float* b0 = (const float*)d_in[5];
    const float* w1 = (const float*)d_in[6];
    const float* b1 = (const float*)d_in[7];
    const float* w2 = (const float*)d_in[8];
    const float* b2 = (const float*)d_in[9];
    const float* w3 = (const float*)d_in[10];
    const float* b3 = (const float*)d_in[11];
    const float* wc = (const float*)d_in[12];
    const float* bc = (const float*)d_in[13];

    int N = in_sizes[0] / 3;
    float* out = (float*)d_out;

    __half *hA, *hB, *whp, *wcp;
    cudaGetSymbolAddress((void**)&hA, g_hA);
    cudaGetSymbolAddress((void**)&hB, g_hB);
    cudaGetSymbolAddress((void**)&whp, g_wh);
    cudaGetSymbolAddress((void**)&wcp, g_wc16);

    cudaFuncSetAttribute(mma512_kernel, cudaFuncAttributeMaxDynamicSharedMemorySize, SM_MMA);
    cudaFuncSetAttribute(mma27_kernel, cudaFuncAttributeMaxDynamicSharedMemorySize, SM_27);

    static cudaStream_t s2 = nullptr;
    static cudaEvent_t evFork = nullptr, evJoin = nullptr;
    if (s2 == nullptr) {
        cudaStreamCreateWithFlags(&s2, cudaStreamNonBlocking);
        cudaEventCreateWithFlags(&evFork, cudaEventDisableTiming);
        cudaEventCreateWithFlags(&evJoin, cudaEventDisableTiming);
    }

    __half* w1h = whp + 0 * 262144;
    __half* w2h = whp + 1 * 262144;
    __half* w3h = whp + 2 * 262144;

    // fork: SH dot kernel runs concurrently with the MLP chain (148 CTAs,
    // grid-stride: minimal SM-slot footprint so mma512 keeps 2 CTA/SM)
    cudaEventRecord(evFork, 0);
    cudaStreamWaitEvent(s2, evFork, 0);
    sh_kernel<<<148, 256, 0, s2>>>(normals, view_dirs, feature, ref_SH, out, N);
    cudaEventRecord(evJoin, s2);

    // main chain (tensor-bound) — R12-proven order
    cvtw_kernel<<<3 * 262144 / 256, 256>>>(w1, w2, w3, whp);
    cvtwc_kernel<<<64, 256>>>(wc, wcp);
    layer0_kernel<<<N / 128, 256>>>(normals, view_dirs, feature, w0, b0, hA, N);

    dim3 gm(4, N / 128);
    mma512_kernel<<<gm, 256, SM_MMA>>>(hA, w1h, b1, hB);
    mma512_kernel<<<gm, 256, SM_MMA>>>(hB, w2h, b2, hA);
    mma512_kernel<<<gm, 256, SM_MMA>>>(hA, w3h, b3, hB);

    // join before fused mma27+finalize (it reads sh outputs)
    cudaStreamWaitEvent(0, evJoin, 0);
    mma27_kernel<<<N / 128, 256, SM_27>>>(hB, wcp, bc, feature, out, N);
}